// round 1
// baseline (speedup 1.0000x reference)
#include <cuda_runtime.h>

// Problem constants (fixed by reference)
#define CN 64
#define HN 256
#define WN 256
#define L0N 1024   // g0 length (y samples), output innermost dim
#define L1N 1024   // g1 length (x samples)
#define AC (-0.75f)

// Scratch: Yt[c][x][j] — y-interpolated, transposed so j is contiguous. 64 MB.
__device__ float g_Yt[CN * WN * L0N];
// Precomputed tap indices / weights
__device__ int   g_yidx[L0N * 4];
__device__ float g_ywt [L0N * 4];
__device__ int   g_xidx[L1N * 4];
__device__ float g_xwt [L1N * 4];

__device__ __forceinline__ void cubic_w(float t, float* w) {
    // Matches reference _cubic_weights exactly (A = -0.75)
    float t2 = t * t;
    float t3 = t2 * t;
    w[0] = AC * (t3 - 2.0f * t2 + t);
    w[1] = (AC + 2.0f) * t3 - (AC + 3.0f) * t2 + 1.0f;
    float s  = 1.0f - t;
    float s2 = s * s;
    w[2] = (AC + 2.0f) * s2 * s - (AC + 3.0f) * s2 + 1.0f;
    float u = 1.0f + s;
    w[3] = AC * (u * u * u) - 5.0f * AC * (u * u) + 8.0f * AC * u - 4.0f * AC;
}

__device__ __forceinline__ void prep_one(float g, int size, int* idx, float* w) {
    float x  = (g + 1.0f) * 0.5f * (float)(size - 1);
    float x0 = floorf(x);
    float t  = x - x0;
    int i0 = (int)x0;
    cubic_w(t, w);
#pragma unroll
    for (int b = 0; b < 4; b++) {
        int ix = i0 - 1 + b;
        ix = min(max(ix, 0), size - 1);   // border padding
        idx[b] = ix;
    }
}

__global__ void prep_kernel(const float* __restrict__ g0,
                            const float* __restrict__ g1) {
    int tid = blockIdx.x * blockDim.x + threadIdx.x;
    if (tid < L0N) {
        int idx[4]; float w[4];
        prep_one(g0[tid], HN, idx, w);
#pragma unroll
        for (int b = 0; b < 4; b++) {
            g_yidx[tid * 4 + b] = idx[b];
            g_ywt [tid * 4 + b] = w[b];
        }
    } else if (tid < L0N + L1N) {
        int i = tid - L0N;
        int idx[4]; float w[4];
        prep_one(g1[i], WN, idx, w);
#pragma unroll
        for (int b = 0; b < 4; b++) {
            g_xidx[i * 4 + b] = idx[b];
            g_xwt [i * 4 + b] = w[b];
        }
    }
}

// Pass 1: Yt[c][x][j] = sum_b wy[j][b] * v[c][yi[j][b]][x]
// 32x32 tile per block: compute with lanes along x (coalesced v reads),
// transpose in smem, store with lanes along j (coalesced Yt writes).
__global__ void pass1_kernel(const float* __restrict__ v) {
    __shared__ float s[32][33];            // [j_local][x_local], padded
    const int tx = threadIdx.x;            // 0..31
    const int ty = threadIdx.y;            // 0..7
    const int c  = blockIdx.z;
    const int xt = blockIdx.x * 32;        // x tile base (W/32 = 8)
    const int jt = blockIdx.y * 32;        // j tile base (L0/32 = 32)

    const float* vc = v + (size_t)c * HN * WN;

#pragma unroll
    for (int r = 0; r < 4; r++) {
        const int jl = ty + r * 8;
        const int j  = jt + jl;
        const int   yi0 = g_yidx[j * 4 + 0];
        const int   yi1 = g_yidx[j * 4 + 1];
        const int   yi2 = g_yidx[j * 4 + 2];
        const int   yi3 = g_yidx[j * 4 + 3];
        const float w0  = g_ywt [j * 4 + 0];
        const float w1  = g_ywt [j * 4 + 1];
        const float w2  = g_ywt [j * 4 + 2];
        const float w3  = g_ywt [j * 4 + 3];
        const int x = xt + tx;
        float acc;
        acc  = w0 * vc[yi0 * WN + x];
        acc += w1 * vc[yi1 * WN + x];
        acc += w2 * vc[yi2 * WN + x];
        acc += w3 * vc[yi3 * WN + x];
        s[jl][tx] = acc;
    }
    __syncthreads();
#pragma unroll
    for (int r = 0; r < 4; r++) {
        const int xl = ty + r * 8;
        g_Yt[((size_t)c * WN + (xt + xl)) * L0N + (jt + tx)] = s[tx][xl];
    }
}

// Pass 2: out[c][i][j] = sum_a wx[i][a] * Yt[c][xi[i][a]][j]
// One block per (i, c); 256 threads cover all 1024 j via float4.
__global__ void pass2_kernel(float* __restrict__ out) {
    const int j = threadIdx.x * 4;         // blockDim.x = 256 -> j in [0,1024)
    const int i = blockIdx.x;
    const int c = blockIdx.y;

    const int   xi0 = g_xidx[i * 4 + 0];
    const int   xi1 = g_xidx[i * 4 + 1];
    const int   xi2 = g_xidx[i * 4 + 2];
    const int   xi3 = g_xidx[i * 4 + 3];
    const float w0  = g_xwt [i * 4 + 0];
    const float w1  = g_xwt [i * 4 + 1];
    const float w2  = g_xwt [i * 4 + 2];
    const float w3  = g_xwt [i * 4 + 3];

    const float* base = g_Yt + (size_t)c * WN * L0N;
    float4 a0 = *(const float4*)(base + (size_t)xi0 * L0N + j);
    float4 a1 = *(const float4*)(base + (size_t)xi1 * L0N + j);
    float4 a2 = *(const float4*)(base + (size_t)xi2 * L0N + j);
    float4 a3 = *(const float4*)(base + (size_t)xi3 * L0N + j);

    float4 acc;
    acc.x = w0 * a0.x + w1 * a1.x + w2 * a2.x + w3 * a3.x;
    acc.y = w0 * a0.y + w1 * a1.y + w2 * a2.y + w3 * a3.y;
    acc.z = w0 * a0.z + w1 * a1.z + w2 * a2.z + w3 * a3.z;
    acc.w = w0 * a0.w + w1 * a1.w + w2 * a2.w + w3 * a3.w;

    *(float4*)(out + ((size_t)c * L1N + i) * L0N + j) = acc;
}

extern "C" void kernel_launch(void* const* d_in, const int* in_sizes, int n_in,
                              void* d_out, int out_size) {
    const float* values = (const float*)d_in[0];   // (1,64,256,256)
    const float* g0     = (const float*)d_in[1];   // (1024,)
    const float* g1     = (const float*)d_in[2];   // (1024,)
    float* out = (float*)d_out;                    // (1,64,1024,1024)

    prep_kernel<<<8, 256>>>(g0, g1);

    dim3 b1(32, 8);
    dim3 gr1(WN / 32, L0N / 32, CN);
    pass1_kernel<<<gr1, b1>>>(values);

    dim3 gr2(L1N, CN);
    pass2_kernel<<<gr2, 256>>>(out);
}

// round 2
// speedup vs baseline: 1.4076x; 1.4076x over previous
#include <cuda_runtime.h>

// Problem constants (fixed by reference)
#define CN 64
#define HN 256
#define WN 256
#define L0N 1024   // g0 length (y samples), output innermost dim (j)
#define L1N 1024   // g1 length (x samples), output middle dim (i)
#define AC (-0.75f)

#define JT 64      // j-tile width per block
#define RS 68      // smem row stride in floats (68*4 = 272 B, 16B-aligned, odd/16 -> conflict-free)

// Precomputed tap indices / weights (vectorized for single LDG.128 per lookup)
__device__ int4   g_yidx[L0N];
__device__ float4 g_ywt [L0N];
__device__ int4   g_xidx[L1N];
__device__ float4 g_xwt [L1N];

__device__ __forceinline__ void cubic_w(float t, float* w) {
    // Matches reference _cubic_weights exactly (A = -0.75)
    float t2 = t * t;
    float t3 = t2 * t;
    w[0] = AC * (t3 - 2.0f * t2 + t);
    w[1] = (AC + 2.0f) * t3 - (AC + 3.0f) * t2 + 1.0f;
    float s  = 1.0f - t;
    float s2 = s * s;
    w[2] = (AC + 2.0f) * s2 * s - (AC + 3.0f) * s2 + 1.0f;
    float u = 1.0f + s;
    w[3] = AC * (u * u * u) - 5.0f * AC * (u * u) + 8.0f * AC * u - 4.0f * AC;
}

__device__ __forceinline__ void prep_one(float g, int size, int* idx, float* w) {
    float x  = (g + 1.0f) * 0.5f * (float)(size - 1);
    float x0 = floorf(x);
    float t  = x - x0;
    int i0 = (int)x0;
    cubic_w(t, w);
#pragma unroll
    for (int b = 0; b < 4; b++) {
        int ix = i0 - 1 + b;
        idx[b] = min(max(ix, 0), size - 1);   // border padding
    }
}

__global__ void prep_kernel(const float* __restrict__ g0,
                            const float* __restrict__ g1) {
    int tid = blockIdx.x * blockDim.x + threadIdx.x;
    if (tid < L0N) {
        int idx[4]; float w[4];
        prep_one(g0[tid], HN, idx, w);
        g_yidx[tid] = make_int4(idx[0], idx[1], idx[2], idx[3]);
        g_ywt [tid] = make_float4(w[0], w[1], w[2], w[3]);
    } else if (tid < L0N + L1N) {
        int i = tid - L0N;
        int idx[4]; float w[4];
        prep_one(g1[i], WN, idx, w);
        g_xidx[i] = make_int4(idx[0], idx[1], idx[2], idx[3]);
        g_xwt [i] = make_float4(w[0], w[1], w[2], w[3]);
    }
}

// Fused kernel: one block = (c, j-tile of 64).
// Phase A: sY[x][jl] = sum_b wy[j][b] * v[c][yi[j][b]][x]  for all x in [0,256), jl in [0,64)
// Phase B: out[c][i][jt+jl] = sum_a wx[i][a] * sY[xi[i][a]][jl]  for all i in [0,1024)
__global__ void __launch_bounds__(512, 3)
fused_kernel(const float* __restrict__ v, float* __restrict__ out) {
    extern __shared__ float sY[];          // [256][RS]

    const int tid = threadIdx.x;
    const int lane = tid & 31;
    const int wid  = tid >> 5;             // 0..15
    const int jt = blockIdx.x * JT;        // j tile base
    const int c  = blockIdx.y;

    const float* vc = v + (size_t)c * (HN * WN);

    // ---- Phase A: y-interpolation into smem ----
#pragma unroll
    for (int r = 0; r < 4; r++) {
        const int jl = wid + r * 16;       // 0..63
        const int4   yi = g_yidx[jt + jl];
        const float4 wy = g_ywt [jt + jl];
        const float* r0 = vc + yi.x * WN;
        const float* r1 = vc + yi.y * WN;
        const float* r2 = vc + yi.z * WN;
        const float* r3 = vc + yi.w * WN;
#pragma unroll
        for (int xc = 0; xc < 8; xc++) {
            const int x = xc * 32 + lane;
            float acc = wy.x * __ldg(r0 + x)
                      + wy.y * __ldg(r1 + x)
                      + wy.z * __ldg(r2 + x)
                      + wy.w * __ldg(r3 + x);
            sY[x * RS + jl] = acc;
        }
    }
    __syncthreads();

    // ---- Phase B: x-interpolation, float4 along j ----
    const int jq = (tid & 15) * 4;         // j offset within tile: 0,4,...,60
    const int ib = tid >> 4;               // 0..31
    float* outc = out + ((size_t)c * L1N) * L0N + jt + jq;

#pragma unroll 4
    for (int it = 0; it < 32; it++) {
        const int i = it * 32 + ib;
        const int4   xi = g_xidx[i];
        const float4 wx = g_xwt [i];

        const float4 a0 = *(const float4*)(sY + xi.x * RS + jq);
        const float4 a1 = *(const float4*)(sY + xi.y * RS + jq);
        const float4 a2 = *(const float4*)(sY + xi.z * RS + jq);
        const float4 a3 = *(const float4*)(sY + xi.w * RS + jq);

        float4 acc;
        acc.x = wx.x * a0.x + wx.y * a1.x + wx.z * a2.x + wx.w * a3.x;
        acc.y = wx.x * a0.y + wx.y * a1.y + wx.z * a2.y + wx.w * a3.y;
        acc.z = wx.x * a0.z + wx.y * a1.z + wx.z * a2.z + wx.w * a3.z;
        acc.w = wx.x * a0.w + wx.y * a1.w + wx.z * a2.w + wx.w * a3.w;

        *(float4*)(outc + (size_t)i * L0N) = acc;
    }
}

extern "C" void kernel_launch(void* const* d_in, const int* in_sizes, int n_in,
                              void* d_out, int out_size) {
    const float* values = (const float*)d_in[0];   // (1,64,256,256)
    const float* g0     = (const float*)d_in[1];   // (1024,)
    const float* g1     = (const float*)d_in[2];   // (1024,)
    float* out = (float*)d_out;                    // (1,64,1024,1024)

    static int smem_set = 0;
    const int smem_bytes = HN * RS * sizeof(float);  // 256*68*4 = 69632
    if (!smem_set) {
        cudaFuncSetAttribute(fused_kernel,
                             cudaFuncAttributeMaxDynamicSharedMemorySize,
                             smem_bytes);
        smem_set = 1;
    }

    prep_kernel<<<8, 256>>>(g0, g1);

    dim3 grid(L0N / JT, CN);               // (16, 64) = 1024 blocks
    fused_kernel<<<grid, 512, smem_bytes>>>(values, out);
}

// round 3
// speedup vs baseline: 1.4119x; 1.0030x over previous
#include <cuda_runtime.h>

// Problem constants (fixed by reference)
#define CN 64
#define HN 256
#define WN 256
#define L0N 1024   // g0 length (y samples), output innermost dim (j)
#define L1N 1024   // g1 length (x samples), output middle dim (i)
#define AC (-0.75f)

#define JT 64      // j-tile width per block
#define RS 68      // smem row stride in floats (16B-aligned; lane-bank stride 4 -> 4-way STS, minor)
#define NB 256     // x0 bins

// Precomputed y tap indices / weights
__device__ int4   g_yidx[L0N];
__device__ float4 g_ywt [L0N];
// x samples sorted by x0 bin (counting sort)
__device__ int    g_binstart[NB + 1];
__device__ float4 g_swx[L1N];   // weights in sorted order
__device__ int    g_si [L1N];   // original i in sorted order

__device__ __forceinline__ void cubic_w(float t, float* w) {
    // Matches reference _cubic_weights exactly (A = -0.75)
    float t2 = t * t;
    float t3 = t2 * t;
    w[0] = AC * (t3 - 2.0f * t2 + t);
    w[1] = (AC + 2.0f) * t3 - (AC + 3.0f) * t2 + 1.0f;
    float s  = 1.0f - t;
    float s2 = s * s;
    w[2] = (AC + 2.0f) * s2 * s - (AC + 3.0f) * s2 + 1.0f;
    float u = 1.0f + s;
    w[3] = AC * (u * u * u) - 5.0f * AC * (u * u) + 8.0f * AC * u - 4.0f * AC;
}

// Single-block prep: y tables + counting sort of x samples by x0.
__global__ void prep_kernel(const float* __restrict__ g0,
                            const float* __restrict__ g1) {
    __shared__ int sh_hist[NB];
    __shared__ int sh_base[NB];
    const int tid = threadIdx.x;   // 0..1023

    // --- y taps ---
    {
        float x  = (g0[tid] + 1.0f) * 0.5f * (float)(HN - 1);
        float x0 = floorf(x);
        float t  = x - x0;
        int  i0  = (int)x0;
        float w[4];
        cubic_w(t, w);
        int idx[4];
#pragma unroll
        for (int b = 0; b < 4; b++) idx[b] = min(max(i0 - 1 + b, 0), HN - 1);
        g_yidx[tid] = make_int4(idx[0], idx[1], idx[2], idx[3]);
        g_ywt [tid] = make_float4(w[0], w[1], w[2], w[3]);
    }

    // --- x taps: bin by x0, counting sort ---
    float x  = (g1[tid] + 1.0f) * 0.5f * (float)(WN - 1);
    float x0 = floorf(x);
    float t  = x - x0;
    int bin  = min(max((int)x0, 0), NB - 1);
    float w[4];
    cubic_w(t, w);

    if (tid < NB) sh_hist[tid] = 0;
    __syncthreads();
    int rank = atomicAdd(&sh_hist[bin], 1);
    __syncthreads();
    if (tid == 0) {
        int s = 0;
        for (int b = 0; b < NB; b++) {
            sh_base[b] = s;
            g_binstart[b] = s;
            s += sh_hist[b];
        }
        g_binstart[NB] = s;
    }
    __syncthreads();
    int pos = sh_base[bin] + rank;
    g_swx[pos] = make_float4(w[0], w[1], w[2], w[3]);
    g_si [pos] = tid;
}

// Fused kernel: one block = (c, 64-wide j tile).
// Phase A: sY[x][jl] = sum_b wy[j][b] * v[c][yi[j][b]][x]
// Phase B: iterate x0 bins; load 4 tap rows once per bin, reuse across all
//          i's in the bin (same taps, different weights).
__global__ void __launch_bounds__(512, 3)
fused_kernel(const float* __restrict__ v, float* __restrict__ out) {
    extern __shared__ float sY[];          // [256][RS]

    const int tid  = threadIdx.x;
    const int lane = tid & 31;
    const int wid  = tid >> 5;             // 0..15
    const int jt = blockIdx.x * JT;        // j tile base
    const int c  = blockIdx.y;

    const float* vc = v + (size_t)c * (HN * WN);

    // ---- Phase A: y-interpolation into smem ----
#pragma unroll
    for (int r = 0; r < 4; r++) {
        const int jl = wid + r * 16;       // 0..63
        const int4   yi = g_yidx[jt + jl];
        const float4 wy = g_ywt [jt + jl];
        const float* r0 = vc + yi.x * WN;
        const float* r1 = vc + yi.y * WN;
        const float* r2 = vc + yi.z * WN;
        const float* r3 = vc + yi.w * WN;
#pragma unroll
        for (int xc = 0; xc < 8; xc++) {
            const int x = xc * 32 + lane;
            float acc = wy.x * __ldg(r0 + x)
                      + wy.y * __ldg(r1 + x)
                      + wy.z * __ldg(r2 + x)
                      + wy.w * __ldg(r3 + x);
            sY[x * RS + jl] = acc;
        }
    }
    __syncthreads();

    // ---- Phase B: bin-shared taps ----
    // Half-warp owns a bin: slot = wid*2 + (lane>>4), 32 slots sweep 256 bins in 8 steps.
    const int slot = (wid << 1) + (lane >> 4);
    const int jq   = (lane & 15) * 4;      // j offset in tile: 0..60
    float* outc = out + ((size_t)c * L1N) * L0N + jt + jq;

    for (int b = slot; b < NB; b += 32) {
        const int s = g_binstart[b];
        const int e = g_binstart[b + 1];
        if (s == e) continue;

        const int r0 = max(b - 1, 0);
        const int r2 = min(b + 1, WN - 1);
        const int r3 = min(b + 2, WN - 1);

        const float4 a0 = *(const float4*)(sY + r0 * RS + jq);
        const float4 a1 = *(const float4*)(sY + b  * RS + jq);
        const float4 a2 = *(const float4*)(sY + r2 * RS + jq);
        const float4 a3 = *(const float4*)(sY + r3 * RS + jq);

        for (int k = s; k < e; k++) {
            const int    i  = g_si [k];
            const float4 wx = g_swx[k];
            float4 acc;
            acc.x = wx.x * a0.x + wx.y * a1.x + wx.z * a2.x + wx.w * a3.x;
            acc.y = wx.x * a0.y + wx.y * a1.y + wx.z * a2.y + wx.w * a3.y;
            acc.z = wx.x * a0.z + wx.y * a1.z + wx.z * a2.z + wx.w * a3.z;
            acc.w = wx.x * a0.w + wx.y * a1.w + wx.z * a2.w + wx.w * a3.w;
            *(float4*)(outc + (size_t)i * L0N) = acc;
        }
    }
}

extern "C" void kernel_launch(void* const* d_in, const int* in_sizes, int n_in,
                              void* d_out, int out_size) {
    const float* values = (const float*)d_in[0];   // (1,64,256,256)
    const float* g0     = (const float*)d_in[1];   // (1024,)
    const float* g1     = (const float*)d_in[2];   // (1024,)
    float* out = (float*)d_out;                    // (1,64,1024,1024)

    static int smem_set = 0;
    const int smem_bytes = HN * RS * sizeof(float);  // 256*68*4 = 69632
    if (!smem_set) {
        cudaFuncSetAttribute(fused_kernel,
                             cudaFuncAttributeMaxDynamicSharedMemorySize,
                             smem_bytes);
        smem_set = 1;
    }

    prep_kernel<<<1, 1024>>>(g0, g1);

    dim3 grid(L0N / JT, CN);               // (16, 64) = 1024 blocks
    fused_kernel<<<grid, 512, smem_bytes>>>(values, out);
}

// round 4
// speedup vs baseline: 1.5675x; 1.1102x over previous
#include <cuda_runtime.h>

// Problem constants (fixed by reference)
#define CN 64
#define HN 256
#define WN 256
#define L0N 1024   // g0 length (y samples), output innermost dim (j)
#define L1N 1024   // g1 length (x samples), output middle dim (i)
#define AC (-0.75f)

#define JT 64      // j-tile width per block
#define RS 66      // smem row stride in floats: 66 mod 32 = 2 -> 2-way STS conflict, float2-aligned
#define NB 256     // x0 bins

// Precomputed y tap indices / weights
__device__ int4   g_yidx[L0N];
__device__ float4 g_ywt [L0N];
// x samples sorted by x0 bin (counting sort)
__device__ int    g_binstart[NB + 1];
__device__ float4 g_swx[L1N];   // weights in sorted order
__device__ int    g_si [L1N];   // original i in sorted order

__device__ __forceinline__ void cubic_w(float t, float* w) {
    // Matches reference _cubic_weights exactly (A = -0.75)
    float t2 = t * t;
    float t3 = t2 * t;
    w[0] = AC * (t3 - 2.0f * t2 + t);
    w[1] = (AC + 2.0f) * t3 - (AC + 3.0f) * t2 + 1.0f;
    float s  = 1.0f - t;
    float s2 = s * s;
    w[2] = (AC + 2.0f) * s2 * s - (AC + 3.0f) * s2 + 1.0f;
    float u = 1.0f + s;
    w[3] = AC * (u * u * u) - 5.0f * AC * (u * u) + 8.0f * AC * u - 4.0f * AC;
}

// Single-block prep: y tables + counting sort of x samples by x0 (parallel scan).
__global__ void prep_kernel(const float* __restrict__ g0,
                            const float* __restrict__ g1) {
    __shared__ int sh_hist[NB];
    __shared__ int sh_scan[NB];
    __shared__ int sh_base[NB];
    const int tid = threadIdx.x;   // 0..1023

    // --- y taps ---
    {
        float x  = (g0[tid] + 1.0f) * 0.5f * (float)(HN - 1);
        float x0 = floorf(x);
        float t  = x - x0;
        int  i0  = (int)x0;
        float w[4];
        cubic_w(t, w);
        int idx[4];
#pragma unroll
        for (int b = 0; b < 4; b++) idx[b] = min(max(i0 - 1 + b, 0), HN - 1);
        g_yidx[tid] = make_int4(idx[0], idx[1], idx[2], idx[3]);
        g_ywt [tid] = make_float4(w[0], w[1], w[2], w[3]);
    }

    // --- x taps: bin by x0, counting sort ---
    float x  = (g1[tid] + 1.0f) * 0.5f * (float)(WN - 1);
    float x0 = floorf(x);
    float t  = x - x0;
    int bin  = min(max((int)x0, 0), NB - 1);
    float w[4];
    cubic_w(t, w);

    if (tid < NB) sh_hist[tid] = 0;
    __syncthreads();
    int rank = atomicAdd(&sh_hist[bin], 1);
    __syncthreads();

    // Parallel inclusive scan (Hillis-Steele) over 256 bins
    if (tid < NB) sh_scan[tid] = sh_hist[tid];
    __syncthreads();
#pragma unroll
    for (int off = 1; off < NB; off <<= 1) {
        int v = 0;
        if (tid < NB && tid >= off) v = sh_scan[tid - off];
        __syncthreads();
        if (tid < NB) sh_scan[tid] += v;
        __syncthreads();
    }
    if (tid < NB) {
        int base = sh_scan[tid] - sh_hist[tid];   // exclusive
        sh_base[tid] = base;
        g_binstart[tid] = base;
        if (tid == NB - 1) g_binstart[NB] = sh_scan[tid];
    }
    __syncthreads();

    int pos = sh_base[bin] + rank;
    g_swx[pos] = make_float4(w[0], w[1], w[2], w[3]);
    g_si [pos] = tid;
}

// Fused kernel: one block = (c, 64-wide j tile).
// Phase A: sY[x][jl] = sum_b wy[j][b] * v[c][yi[j][b]][x]
// Phase B: full warp per x0-bin; lanes cover 64 j as float2. Taps loaded once
//          per bin, reused across all i's in the bin.
__global__ void __launch_bounds__(512, 3)
fused_kernel(const float* __restrict__ v, float* __restrict__ out) {
    extern __shared__ float sY[];          // [256][RS]

    const int tid  = threadIdx.x;
    const int lane = tid & 31;
    const int wid  = tid >> 5;             // 0..15
    const int jt = blockIdx.x * JT;        // j tile base
    const int c  = blockIdx.y;

    const float* vc = v + (size_t)c * (HN * WN);

    // ---- Phase A: y-interpolation into smem ----
#pragma unroll
    for (int r = 0; r < 4; r++) {
        const int jl = wid + r * 16;       // 0..63
        const int4   yi = g_yidx[jt + jl];
        const float4 wy = g_ywt [jt + jl];
        const float* r0 = vc + yi.x * WN;
        const float* r1 = vc + yi.y * WN;
        const float* r2 = vc + yi.z * WN;
        const float* r3 = vc + yi.w * WN;
#pragma unroll
        for (int xc = 0; xc < 8; xc++) {
            const int x = xc * 32 + lane;
            float acc = wy.x * __ldg(r0 + x)
                      + wy.y * __ldg(r1 + x)
                      + wy.z * __ldg(r2 + x)
                      + wy.w * __ldg(r3 + x);
            sY[x * RS + jl] = acc;
        }
    }
    __syncthreads();

    // ---- Phase B: one warp per bin, float2 along j ----
    const int jq = lane * 2;               // j offset in tile: 0..62
    float* outc = out + ((size_t)c * L1N) * L0N + jt + jq;

#pragma unroll
    for (int t = 0; t < 16; t++) {
        const int b = wid + t * 16;
        const int s = g_binstart[b];
        const int e = g_binstart[b + 1];
        if (s == e) continue;

        const int rr0 = max(b - 1, 0);
        const int rr2 = min(b + 1, WN - 1);
        const int rr3 = min(b + 2, WN - 1);

        const float2 a0 = *(const float2*)(sY + rr0 * RS + jq);
        const float2 a1 = *(const float2*)(sY + b   * RS + jq);
        const float2 a2 = *(const float2*)(sY + rr2 * RS + jq);
        const float2 a3 = *(const float2*)(sY + rr3 * RS + jq);

        int k = s;
        for (; k + 1 < e; k += 2) {
            const int    iA  = g_si [k];
            const float4 wxA = g_swx[k];
            const int    iB  = g_si [k + 1];
            const float4 wxB = g_swx[k + 1];
            float2 accA, accB;
            accA.x = wxA.x * a0.x + wxA.y * a1.x + wxA.z * a2.x + wxA.w * a3.x;
            accA.y = wxA.x * a0.y + wxA.y * a1.y + wxA.z * a2.y + wxA.w * a3.y;
            accB.x = wxB.x * a0.x + wxB.y * a1.x + wxB.z * a2.x + wxB.w * a3.x;
            accB.y = wxB.x * a0.y + wxB.y * a1.y + wxB.z * a2.y + wxB.w * a3.y;
            *(float2*)(outc + (size_t)iA * L0N) = accA;
            *(float2*)(outc + (size_t)iB * L0N) = accB;
        }
        if (k < e) {
            const int    i  = g_si [k];
            const float4 wx = g_swx[k];
            float2 acc;
            acc.x = wx.x * a0.x + wx.y * a1.x + wx.z * a2.x + wx.w * a3.x;
            acc.y = wx.x * a0.y + wx.y * a1.y + wx.z * a2.y + wx.w * a3.y;
            *(float2*)(outc + (size_t)i * L0N) = acc;
        }
    }
}

extern "C" void kernel_launch(void* const* d_in, const int* in_sizes, int n_in,
                              void* d_out, int out_size) {
    const float* values = (const float*)d_in[0];   // (1,64,256,256)
    const float* g0     = (const float*)d_in[1];   // (1024,)
    const float* g1     = (const float*)d_in[2];   // (1024,)
    float* out = (float*)d_out;                    // (1,64,1024,1024)

    static int smem_set = 0;
    const int smem_bytes = HN * RS * sizeof(float);  // 256*66*4 = 67584
    if (!smem_set) {
        cudaFuncSetAttribute(fused_kernel,
                             cudaFuncAttributeMaxDynamicSharedMemorySize,
                             smem_bytes);
        smem_set = 1;
    }

    prep_kernel<<<1, 1024>>>(g0, g1);

    dim3 grid(L0N / JT, CN);               // (16, 64) = 1024 blocks
    fused_kernel<<<grid, 512, smem_bytes>>>(values, out);
}